// round 1
// baseline (speedup 1.0000x reference)
#include <cuda_runtime.h>

typedef unsigned long long ULL;

// ---------- packed f32x2 helpers (Blackwell sm_103a) ----------
__device__ __forceinline__ ULL f2x2_fma(ULL a, ULL b, ULL c) {
    ULL d;
    asm("fma.rn.f32x2 %0, %1, %2, %3;" : "=l"(d) : "l"(a), "l"(b), "l"(c));
    return d;
}
__device__ __forceinline__ ULL f2x2_dup(float x) {
    ULL p;
    asm("mov.b64 %0, {%1, %2};" : "=l"(p) : "f"(x), "f"(x));
    return p;
}
__device__ __forceinline__ void f2x2_unpack(ULL v, float& lo, float& hi) {
    asm("mov.b64 {%0, %1}, %2;" : "=f"(lo), "=f"(hi) : "l"(v));
}

// ---------- problem constants (fixed instance) ----------
constexpr int S = 3, G = 8, B = 2048, C = 512, P = 64;
constexpr int N = S * G * B;              // 49152
constexpr int OUT_ELEMS = G * P * C;      // 262144
constexpr int KTOT = S * B;               // 6144 rows per graph
constexpr int KS = 7;                     // split-K for GEMM2
constexpr int KCHUNK = 880;               // 7*880 >= 6144, multiple of 16

// ---------- device scratch (no allocations allowed) ----------
__device__ float g_csq[P];
__device__ float g_ivb[P];
__device__ float g_partial[(size_t)KS * OUT_ELEMS];

// ---------- prep: |c|^2 and 1/beta ----------
__global__ void prep_kernel(const float* __restrict__ W, const float* __restrict__ sf) {
    int p = threadIdx.x;
    if (p >= P) return;
    const float4* wr = reinterpret_cast<const float4*>(W + (size_t)p * C);
    float s = 0.f;
#pragma unroll 8
    for (int i = 0; i < C / 4; i++) {
        float4 v = wr[i];
        s += v.x * v.x + v.y * v.y + v.z * v.z + v.w * v.w;
    }
    g_csq[p] = s;
    g_ivb[p] = 1.0f + __expf(-sf[p]);   // 1/sigmoid(sf)
}

// ---------- fused GEMM1 + softmax -> assign [N, P] ----------
constexpr int BM = 128;       // rows per block
constexpr int KC = 16;        // k per stage
constexpr int NSTG = C / KC;  // 32

__global__ __launch_bounds__(128) void assign_kernel(
    const float* __restrict__ X, const float* __restrict__ W,
    float* __restrict__ assign_out)
{
    __shared__ __align__(16) float As[2][KC][BM];
    __shared__ __align__(16) float Ws[2][KC][P];
    __shared__ __align__(16) float Lg[BM][P + 1];
    __shared__ float Xsq[BM];
    __shared__ float Csq[P];
    __shared__ float Ivb[P];

    const int t = threadIdx.x;
    const int row_base = blockIdx.x * BM;
    const int r0 = (t >> 3) * 8;   // 8 rows (4 f32x2 row-pairs)
    const int c0 = (t & 7) * 8;    // 8 cols
    const int wp = t & 63;         // p index owned for W loads
    const int wh = t >> 6;         // which 8 of the 16 k's

    if (t < P) { Csq[t] = g_csq[t]; Ivb[t] = g_ivb[t]; }

    const float* xrow = X + (size_t)(row_base + t) * C;   // thread t owns row t
    const float* wrow = W + (size_t)wp * C + wh * 8;

    ULL acc[4][8];
#pragma unroll
    for (int i = 0; i < 4; i++)
#pragma unroll
        for (int j = 0; j < 8; j++) acc[i][j] = 0ull;

    float xsq = 0.f;
    float4 al[4], wl[2];

    // prologue: stage 0 global loads + smem store
#pragma unroll
    for (int i = 0; i < 4; i++) al[i] = *reinterpret_cast<const float4*>(xrow + i * 4);
    wl[0] = *reinterpret_cast<const float4*>(wrow);
    wl[1] = *reinterpret_cast<const float4*>(wrow + 4);
#pragma unroll
    for (int i = 0; i < 4; i++) {
        As[0][i * 4 + 0][t] = al[i].x; As[0][i * 4 + 1][t] = al[i].y;
        As[0][i * 4 + 2][t] = al[i].z; As[0][i * 4 + 3][t] = al[i].w;
        xsq += al[i].x * al[i].x + al[i].y * al[i].y + al[i].z * al[i].z + al[i].w * al[i].w;
    }
#pragma unroll
    for (int h = 0; h < 2; h++) {
        Ws[0][wh * 8 + h * 4 + 0][wp] = wl[h].x;
        Ws[0][wh * 8 + h * 4 + 1][wp] = wl[h].y;
        Ws[0][wh * 8 + h * 4 + 2][wp] = wl[h].z;
        Ws[0][wh * 8 + h * 4 + 3][wp] = wl[h].w;
    }
    __syncthreads();

#pragma unroll 1
    for (int s = 0; s < NSTG; s++) {
        const int buf = s & 1;
        if (s + 1 < NSTG) {
            const int k0 = (s + 1) * KC;
#pragma unroll
            for (int i = 0; i < 4; i++)
                al[i] = *reinterpret_cast<const float4*>(xrow + k0 + i * 4);
            wl[0] = *reinterpret_cast<const float4*>(wrow + k0);
            wl[1] = *reinterpret_cast<const float4*>(wrow + k0 + 4);
        }
#pragma unroll
        for (int kk = 0; kk < KC; kk++) {
            ulonglong2 a01 = *reinterpret_cast<const ulonglong2*>(&As[buf][kk][r0]);
            ulonglong2 a23 = *reinterpret_cast<const ulonglong2*>(&As[buf][kk][r0 + 4]);
            float4 b0 = *reinterpret_cast<const float4*>(&Ws[buf][kk][c0]);
            float4 b1 = *reinterpret_cast<const float4*>(&Ws[buf][kk][c0 + 4]);
            ULL bd[8];
            bd[0] = f2x2_dup(b0.x); bd[1] = f2x2_dup(b0.y);
            bd[2] = f2x2_dup(b0.z); bd[3] = f2x2_dup(b0.w);
            bd[4] = f2x2_dup(b1.x); bd[5] = f2x2_dup(b1.y);
            bd[6] = f2x2_dup(b1.z); bd[7] = f2x2_dup(b1.w);
            ULL av[4] = {a01.x, a01.y, a23.x, a23.y};
#pragma unroll
            for (int i = 0; i < 4; i++)
#pragma unroll
                for (int j = 0; j < 8; j++)
                    acc[i][j] = f2x2_fma(av[i], bd[j], acc[i][j]);
        }
        if (s + 1 < NSTG) {
            const int nb = buf ^ 1;
#pragma unroll
            for (int i = 0; i < 4; i++) {
                As[nb][i * 4 + 0][t] = al[i].x; As[nb][i * 4 + 1][t] = al[i].y;
                As[nb][i * 4 + 2][t] = al[i].z; As[nb][i * 4 + 3][t] = al[i].w;
                xsq += al[i].x * al[i].x + al[i].y * al[i].y + al[i].z * al[i].z + al[i].w * al[i].w;
            }
#pragma unroll
            for (int h = 0; h < 2; h++) {
                Ws[nb][wh * 8 + h * 4 + 0][wp] = wl[h].x;
                Ws[nb][wh * 8 + h * 4 + 1][wp] = wl[h].y;
                Ws[nb][wh * 8 + h * 4 + 2][wp] = wl[h].z;
                Ws[nb][wh * 8 + h * 4 + 3][wp] = wl[h].w;
            }
        }
        __syncthreads();
    }

    // dump cx tile to smem, plus |x|^2
#pragma unroll
    for (int i = 0; i < 4; i++)
#pragma unroll
        for (int j = 0; j < 8; j++) {
            float lo, hi;
            f2x2_unpack(acc[i][j], lo, hi);
            Lg[r0 + 2 * i][c0 + j] = lo;
            Lg[r0 + 2 * i + 1][c0 + j] = hi;
        }
    Xsq[t] = xsq;
    __syncthreads();

    // softmax: thread t owns row t
    float l[P];
    const float xs = Xsq[t];
    float m = -3.402823e38f;
#pragma unroll
    for (int p = 0; p < P; p++) {
        float v = fminf(2.f * Lg[t][p] - xs - Csq[p], 0.f) * Ivb[p];
        l[p] = v;
        m = fmaxf(m, v);
    }
    float sum = 0.f;
#pragma unroll
    for (int p = 0; p < P; p++) { float e = __expf(l[p] - m); l[p] = e; sum += e; }
    const float inv = 1.f / sum;
    float4* orow = reinterpret_cast<float4*>(assign_out + (size_t)(row_base + t) * P);
#pragma unroll
    for (int q = 0; q < P / 4; q++)
        orow[q] = make_float4(l[4 * q] * inv, l[4 * q + 1] * inv,
                              l[4 * q + 2] * inv, l[4 * q + 3] * inv);
}

// ---------- GEMM2: out[g] = assign_g^T @ feats_g  (split-K partials) ----------
constexpr int BC2 = 64;
constexpr int KC2 = 16;
constexpr int NST2 = KCHUNK / KC2;   // 55

__global__ __launch_bounds__(128) void gemm2_kernel(
    const float* __restrict__ X, const float* __restrict__ Asn)
{
    __shared__ __align__(16) float Asm[2][KC2][P];
    __shared__ __align__(16) float Fsm[2][KC2][BC2];

    const int t = threadIdx.x;
    const int ct = blockIdx.x;   // c tile 0..7
    const int g  = blockIdx.y;   // graph 0..7
    const int ks = blockIdx.z;   // k split 0..6

    const int p0 = (t >> 3) * 4;   // 4 p rows
    const int c0 = (t & 7) * 8;    // 8 cols = 4 f32x2 col-pairs

    const int jj = t >> 3;         // k-row within stage (0..15)
    const int part = t & 7;        // 8-float chunk (0..7)

    const int j0 = ks * KCHUNK;
    const int cbase = ct * BC2;

    ULL acc[4][4];
#pragma unroll
    for (int i = 0; i < 4; i++)
#pragma unroll
        for (int j = 0; j < 4; j++) acc[i][j] = 0ull;

    float4 aa[2], ff[2];

    auto load_stage = [&](int stg) {
        const int j = j0 + stg * KC2 + jj;
        if (j < KTOT) {
            const int sidx = j >> 11;            // / B (2048)
            const int n = j & (B - 1);
            const size_t row = (size_t)sidx * (G * B) + (size_t)g * B + n;
            const float* ap = Asn + row * P + part * 8;
            const float* fp = X + row * C + cbase + part * 8;
            aa[0] = *reinterpret_cast<const float4*>(ap);
            aa[1] = *reinterpret_cast<const float4*>(ap + 4);
            ff[0] = *reinterpret_cast<const float4*>(fp);
            ff[1] = *reinterpret_cast<const float4*>(fp + 4);
        } else {
            aa[0] = aa[1] = ff[0] = ff[1] = make_float4(0.f, 0.f, 0.f, 0.f);
        }
    };
    auto store_stage = [&](int nb) {
        *reinterpret_cast<float4*>(&Asm[nb][jj][part * 8])     = aa[0];
        *reinterpret_cast<float4*>(&Asm[nb][jj][part * 8 + 4]) = aa[1];
        *reinterpret_cast<float4*>(&Fsm[nb][jj][part * 8])     = ff[0];
        *reinterpret_cast<float4*>(&Fsm[nb][jj][part * 8 + 4]) = ff[1];
    };

    load_stage(0);
    store_stage(0);
    __syncthreads();

#pragma unroll 1
    for (int s = 0; s < NST2; s++) {
        const int buf = s & 1;
        if (s + 1 < NST2) load_stage(s + 1);
#pragma unroll
        for (int kk = 0; kk < KC2; kk++) {
            float4 a = *reinterpret_cast<const float4*>(&Asm[buf][kk][p0]);
            ULL ad[4];
            ad[0] = f2x2_dup(a.x); ad[1] = f2x2_dup(a.y);
            ad[2] = f2x2_dup(a.z); ad[3] = f2x2_dup(a.w);
            ulonglong2 b01 = *reinterpret_cast<const ulonglong2*>(&Fsm[buf][kk][c0]);
            ulonglong2 b23 = *reinterpret_cast<const ulonglong2*>(&Fsm[buf][kk][c0 + 4]);
            ULL bv[4] = {b01.x, b01.y, b23.x, b23.y};
#pragma unroll
            for (int i = 0; i < 4; i++)
#pragma unroll
                for (int j = 0; j < 4; j++)
                    acc[i][j] = f2x2_fma(ad[i], bv[j], acc[i][j]);
        }
        if (s + 1 < NST2) store_stage(buf ^ 1);
        __syncthreads();
    }

    float* dst = g_partial + ((size_t)ks * G + g) * (size_t)(P * C);
#pragma unroll
    for (int i = 0; i < 4; i++) {
        const int p = p0 + i;
#pragma unroll
        for (int j = 0; j < 4; j++) {
            const int c = cbase + c0 + 2 * j;
            *reinterpret_cast<ULL*>(dst + (size_t)p * C + c) = acc[i][j];
        }
    }
}

// ---------- deterministic split-K reduction ----------
__global__ void reduce_kernel(float* __restrict__ out) {
    const int i = blockIdx.x * blockDim.x + threadIdx.x;
    if (i < OUT_ELEMS) {
        float s = 0.f;
#pragma unroll
        for (int ks = 0; ks < KS; ks++) s += g_partial[(size_t)ks * OUT_ELEMS + i];
        out[i] = s;
    }
}

// ---------- launch ----------
extern "C" void kernel_launch(void* const* d_in, const int* in_sizes, int n_in,
                              void* d_out, int out_size) {
    const float* X  = (const float*)d_in[0];   // node_feats [S, G*B, C]
    const float* W  = (const float*)d_in[1];   // weight [P, C]
    const float* sf = (const float*)d_in[2];   // smooth_factor [P]
    float* out = (float*)d_out;                // [outputs (G,P,C) | assign (N,P)]
    float* assign_out = out + OUT_ELEMS;

    prep_kernel<<<1, 64>>>(W, sf);
    assign_kernel<<<N / BM, 128>>>(X, W, assign_out);
    gemm2_kernel<<<dim3(C / BC2, G, KS), 128>>>(X, assign_out);
    reduce_kernel<<<(OUT_ELEMS + 255) / 256, 256>>>(out);
}